// round 11
// baseline (speedup 1.0000x reference)
#include <cuda_runtime.h>
#include <cuda_bf16.h>
#include <cstdint>

// ==========================================================================
// LORI_FC: out = x @ blockdiag(D) + (x @ Wl^T) @ Wr^T + (b_right + bias)
//   x [8192,4096] f32, D [64,64,64], Wl [64,4096], Wr [4096,64]. Output f32.
// HMMA mma.sync.m16n8k16 bf16, split hi/lo (3 passes), fp32 accum.
// Register-direct fragments: NO shared memory, NO syncthreads.
//   prep: split Wl/Wr/D^T to bf16 hi/lo, bsum = br + bias
//   k1:   t_part[s] = x[:, ks:ks+256] @ Wl[:, ks:ks+256]^T   (1024 CTAs)
//   k1b:  t = sum(t_part), split to bf16 hi/lo
//   k2:   out[128,64j] = xb_j @ D_j + t @ Wr_j^T + bsum      (4096 CTAs)
// ==========================================================================

#define M_ROWS 8192
#define IN_F   4096
#define OUT_F  4096
#define KSPLIT 16

__device__ __align__(16) float g_tpart[KSPLIT][M_ROWS * 64];       // 32 MB
__device__ __align__(16) __nv_bfloat16 g_thi[M_ROWS * 64];
__device__ __align__(16) __nv_bfloat16 g_tlo[M_ROWS * 64];
__device__ __align__(16) __nv_bfloat16 g_wlh[64 * IN_F];
__device__ __align__(16) __nv_bfloat16 g_wll[64 * IN_F];
__device__ __align__(16) __nv_bfloat16 g_wrh[OUT_F * 64];
__device__ __align__(16) __nv_bfloat16 g_wrl[OUT_F * 64];
__device__ __align__(16) __nv_bfloat16 g_dth[64 * 64 * 64];        // [j][n][k]
__device__ __align__(16) __nv_bfloat16 g_dtl[64 * 64 * 64];
__device__ __align__(16) float g_bsum[OUT_F];

#define MMA_BF16(C, A0, A1, A2, A3, B0, B1)                                   \
    asm volatile(                                                             \
        "mma.sync.aligned.m16n8k16.row.col.f32.bf16.bf16.f32 "                \
        "{%0,%1,%2,%3}, {%4,%5,%6,%7}, {%8,%9}, {%0,%1,%2,%3};"               \
        : "+f"((C)[0]), "+f"((C)[1]), "+f"((C)[2]), "+f"((C)[3])              \
        : "r"(A0), "r"(A1), "r"(A2), "r"(A3), "r"(B0), "r"(B1))

// split float2 -> packed bf16x2 hi + lo (lo = exact residual)
__device__ __forceinline__ void split2pack(float f0, float f1,
                                           uint32_t& hi, uint32_t& lo) {
    uint32_t h;
    asm("cvt.rn.bf16x2.f32 %0, %1, %2;" : "=r"(h) : "f"(f1), "f"(f0));
    float h0 = __uint_as_float(h << 16);
    float h1 = __uint_as_float(h & 0xffff0000u);
    float r0 = f0 - h0, r1 = f1 - h1;
    asm("cvt.rn.bf16x2.f32 %0, %1, %2;" : "=r"(lo) : "f"(r1), "f"(r0));
    hi = h;
}

__device__ __forceinline__ uint32_t ld_u32(const __nv_bfloat16* p) {
    return *reinterpret_cast<const uint32_t*>(p);
}

// --------------------------------------------------------------------------
// prep: weight splits + bsum.  grid 3088 x 256.
// --------------------------------------------------------------------------
__global__ void prep(const float* __restrict__ wl, const float* __restrict__ wr,
                     const float* __restrict__ diag, const float* __restrict__ br,
                     const float* __restrict__ bias) {
    int i = blockIdx.x * 256 + threadIdx.x;
    if (i < 262144) {
        float v = wl[i];
        __nv_bfloat16 h = __float2bfloat16(v);
        g_wlh[i] = h;
        g_wll[i] = __float2bfloat16(v - __bfloat162float(h));
    } else if (i < 524288) {
        int k = i - 262144;
        float v = wr[k];
        __nv_bfloat16 h = __float2bfloat16(v);
        g_wrh[k] = h;
        g_wrl[k] = __float2bfloat16(v - __bfloat162float(h));
    } else if (i < 786432) {
        int k = i - 524288;             // dt layout [j][n][kk]
        int j = k >> 12, r = k & 4095, n = r >> 6, kk = r & 63;
        float v = diag[(size_t)j * 4096 + (size_t)kk * 64 + n];
        __nv_bfloat16 h = __float2bfloat16(v);
        g_dth[k] = h;
        g_dtl[k] = __float2bfloat16(v - __bfloat162float(h));
    } else if (i < 786432 + 4096) {
        int k = i - 786432;
        g_bsum[k] = br[k] + bias[k];
    }
}

// --------------------------------------------------------------------------
// k1: t_part[s] = x[:, s*256:(s+1)*256] @ Wl^T slice.
// grid 1024 (= 64 m-tiles x 16 k-splits), 256 threads, no smem.
// Warp tile 32M x 32N, 16 k-frags of 16.
// --------------------------------------------------------------------------
__global__ void __launch_bounds__(256, 2)
k1_lowrank(const float* __restrict__ x) {
    const int tid = threadIdx.x, w = tid >> 5, lane = tid & 31;
    const int g = lane >> 2, q = lane & 3;
    const int m0 = (blockIdx.x >> 4) * 128;
    const int ks = (blockIdx.x & 15) * 256;
    const int mrow = (w & 3) * 32, ncol = (w >> 2) * 32;

    float acc[2][4][4];
#pragma unroll
    for (int mf = 0; mf < 2; mf++)
#pragma unroll
        for (int nf = 0; nf < 4; nf++)
#pragma unroll
            for (int c = 0; c < 4; c++) acc[mf][nf][c] = 0.0f;

    const float* xbase = x + (size_t)(m0 + mrow + g) * IN_F + ks + q * 2;

    for (int kk = 0; kk < 16; kk++) {
        const int k = kk * 16;
        uint32_t ah[2][4], al[2][4];
#pragma unroll
        for (int mf = 0; mf < 2; mf++) {
            const float* p0 = xbase + (size_t)(mf * 16) * IN_F + k;
            const float* p1 = p0 + (size_t)8 * IN_F;
            float2 v0 = *(const float2*)p0;
            float2 v1 = *(const float2*)p1;
            float2 v2 = *(const float2*)(p0 + 8);
            float2 v3 = *(const float2*)(p1 + 8);
            split2pack(v0.x, v0.y, ah[mf][0], al[mf][0]);
            split2pack(v1.x, v1.y, ah[mf][1], al[mf][1]);
            split2pack(v2.x, v2.y, ah[mf][2], al[mf][2]);
            split2pack(v3.x, v3.y, ah[mf][3], al[mf][3]);
        }
        uint32_t bh[4][2], bl[4][2];
#pragma unroll
        for (int nf = 0; nf < 4; nf++) {
            const int n = ncol + nf * 8 + g;
            const __nv_bfloat16* ph = g_wlh + (size_t)n * IN_F + ks + k + q * 2;
            const __nv_bfloat16* pl = g_wll + (size_t)n * IN_F + ks + k + q * 2;
            bh[nf][0] = ld_u32(ph);
            bh[nf][1] = ld_u32(ph + 8);
            bl[nf][0] = ld_u32(pl);
            bl[nf][1] = ld_u32(pl + 8);
        }
#pragma unroll
        for (int mf = 0; mf < 2; mf++)
#pragma unroll
            for (int nf = 0; nf < 4; nf++) {
                MMA_BF16(acc[mf][nf], ah[mf][0], ah[mf][1], ah[mf][2], ah[mf][3],
                         bh[nf][0], bh[nf][1]);
                MMA_BF16(acc[mf][nf], ah[mf][0], ah[mf][1], ah[mf][2], ah[mf][3],
                         bl[nf][0], bl[nf][1]);
                MMA_BF16(acc[mf][nf], al[mf][0], al[mf][1], al[mf][2], al[mf][3],
                         bh[nf][0], bh[nf][1]);
            }
    }

    float* tp = g_tpart[blockIdx.x & 15];
#pragma unroll
    for (int mf = 0; mf < 2; mf++)
#pragma unroll
        for (int nf = 0; nf < 4; nf++) {
            int row = m0 + mrow + mf * 16 + g;
            int col = ncol + nf * 8 + q * 2;
            *(float2*)&tp[(size_t)row * 64 + col] =
                make_float2(acc[mf][nf][0], acc[mf][nf][1]);
            *(float2*)&tp[(size_t)(row + 8) * 64 + col] =
                make_float2(acc[mf][nf][2], acc[mf][nf][3]);
        }
}

// --------------------------------------------------------------------------
// k1b: t = sum of partials, split to bf16 hi/lo.  grid 2048 x 256.
// --------------------------------------------------------------------------
__global__ void k1b_reduce() {
    int i = blockIdx.x * 256 + threadIdx.x;
    float s = 0.0f;
#pragma unroll
    for (int p = 0; p < KSPLIT; p++) s += g_tpart[p][i];
    __nv_bfloat16 h = __float2bfloat16(s);
    g_thi[i] = h;
    g_tlo[i] = __float2bfloat16(s - __bfloat162float(h));
}

// --------------------------------------------------------------------------
// k2: out[m0:m0+128, 64j:64j+64] = xb_j @ D_j + t @ Wr_j^T + bsum
// grid (64 m, 64 j), 256 threads, no smem. Warp tile 32M x 32N.
// --------------------------------------------------------------------------
__global__ void __launch_bounds__(256, 2)
k2_output(const float* __restrict__ x, float* __restrict__ out) {
    const int tid = threadIdx.x, w = tid >> 5, lane = tid & 31;
    const int g = lane >> 2, q = lane & 3;
    const int m0 = blockIdx.x * 128;
    const int j  = blockIdx.y;
    const int mrow = (w & 3) * 32, ncol = (w >> 2) * 32;

    float acc[2][4][4];
#pragma unroll
    for (int mf = 0; mf < 2; mf++)
#pragma unroll
        for (int nf = 0; nf < 4; nf++)
#pragma unroll
            for (int c = 0; c < 4; c++) acc[mf][nf][c] = 0.0f;

    // ---------- GEMM 1: A = x[:, 64j:64j+64] (f32, split in-reg), B = D_j^T
    {
        const float* xbase = x + (size_t)(m0 + mrow + g) * IN_F + j * 64 + q * 2;
        const __nv_bfloat16* dthb = g_dth + (size_t)j * 4096;
        const __nv_bfloat16* dtlb = g_dtl + (size_t)j * 4096;
#pragma unroll
        for (int kk = 0; kk < 4; kk++) {
            const int k = kk * 16;
            uint32_t ah[2][4], al[2][4];
#pragma unroll
            for (int mf = 0; mf < 2; mf++) {
                const float* p0 = xbase + (size_t)(mf * 16) * IN_F + k;
                const float* p1 = p0 + (size_t)8 * IN_F;
                float2 v0 = *(const float2*)p0;
                float2 v1 = *(const float2*)p1;
                float2 v2 = *(const float2*)(p0 + 8);
                float2 v3 = *(const float2*)(p1 + 8);
                split2pack(v0.x, v0.y, ah[mf][0], al[mf][0]);
                split2pack(v1.x, v1.y, ah[mf][1], al[mf][1]);
                split2pack(v2.x, v2.y, ah[mf][2], al[mf][2]);
                split2pack(v3.x, v3.y, ah[mf][3], al[mf][3]);
            }
            uint32_t bh[4][2], bl[4][2];
#pragma unroll
            for (int nf = 0; nf < 4; nf++) {
                const int n = ncol + nf * 8 + g;
                const __nv_bfloat16* ph = dthb + (size_t)n * 64 + k + q * 2;
                const __nv_bfloat16* pl = dtlb + (size_t)n * 64 + k + q * 2;
                bh[nf][0] = ld_u32(ph);
                bh[nf][1] = ld_u32(ph + 8);
                bl[nf][0] = ld_u32(pl);
                bl[nf][1] = ld_u32(pl + 8);
            }
#pragma unroll
            for (int mf = 0; mf < 2; mf++)
#pragma unroll
                for (int nf = 0; nf < 4; nf++) {
                    MMA_BF16(acc[mf][nf], ah[mf][0], ah[mf][1], ah[mf][2], ah[mf][3],
                             bh[nf][0], bh[nf][1]);
                    MMA_BF16(acc[mf][nf], ah[mf][0], ah[mf][1], ah[mf][2], ah[mf][3],
                             bl[nf][0], bl[nf][1]);
                    MMA_BF16(acc[mf][nf], al[mf][0], al[mf][1], al[mf][2], al[mf][3],
                             bh[nf][0], bh[nf][1]);
                }
        }
    }

    // ---------- GEMM 2: A = t (bf16 hi/lo direct), B = Wr_j
    {
        const __nv_bfloat16* thb = g_thi + (size_t)(m0 + mrow + g) * 64 + q * 2;
        const __nv_bfloat16* tlb = g_tlo + (size_t)(m0 + mrow + g) * 64 + q * 2;
#pragma unroll
        for (int kk = 0; kk < 4; kk++) {
            const int k = kk * 16;
            uint32_t ah[2][4], al[2][4];
#pragma unroll
            for (int mf = 0; mf < 2; mf++) {
                const int ro = mf * 16 * 64;
                ah[mf][0] = ld_u32(thb + ro + k);
                ah[mf][1] = ld_u32(thb + ro + 8 * 64 + k);
                ah[mf][2] = ld_u32(thb + ro + k + 8);
                ah[mf][3] = ld_u32(thb + ro + 8 * 64 + k + 8);
                al[mf][0] = ld_u32(tlb + ro + k);
                al[mf][1] = ld_u32(tlb + ro + 8 * 64 + k);
                al[mf][2] = ld_u32(tlb + ro + k + 8);
                al[mf][3] = ld_u32(tlb + ro + 8 * 64 + k + 8);
            }
            uint32_t bh[4][2], bl[4][2];
#pragma unroll
            for (int nf = 0; nf < 4; nf++) {
                const int n = ncol + nf * 8 + g;
                const __nv_bfloat16* ph = g_wrh + (size_t)(j * 64 + n) * 64 + k + q * 2;
                const __nv_bfloat16* pl = g_wrl + (size_t)(j * 64 + n) * 64 + k + q * 2;
                bh[nf][0] = ld_u32(ph);
                bh[nf][1] = ld_u32(ph + 8);
                bl[nf][0] = ld_u32(pl);
                bl[nf][1] = ld_u32(pl + 8);
            }
#pragma unroll
            for (int mf = 0; mf < 2; mf++)
#pragma unroll
                for (int nf = 0; nf < 4; nf++) {
                    MMA_BF16(acc[mf][nf], ah[mf][0], ah[mf][1], ah[mf][2], ah[mf][3],
                             bh[nf][0], bh[nf][1]);
                    MMA_BF16(acc[mf][nf], ah[mf][0], ah[mf][1], ah[mf][2], ah[mf][3],
                             bl[nf][0], bl[nf][1]);
                    MMA_BF16(acc[mf][nf], al[mf][0], al[mf][1], al[mf][2], al[mf][3],
                             bh[nf][0], bh[nf][1]);
                }
        }
    }

    // ---------- epilogue ----------
    const float* bs = g_bsum + j * 64;
#pragma unroll
    for (int mf = 0; mf < 2; mf++)
#pragma unroll
        for (int nf = 0; nf < 4; nf++) {
            int col = ncol + nf * 8 + q * 2;
            int row = m0 + mrow + mf * 16 + g;
            float b0 = bs[col], b1 = bs[col + 1];
            *(float2*)&out[(size_t)row * OUT_F + j * 64 + col] =
                make_float2(acc[mf][nf][0] + b0, acc[mf][nf][1] + b1);
            *(float2*)&out[(size_t)(row + 8) * OUT_F + j * 64 + col] =
                make_float2(acc[mf][nf][2] + b0, acc[mf][nf][3] + b1);
        }
}

// --------------------------------------------------------------------------
extern "C" void kernel_launch(void* const* d_in, const int* in_sizes, int n_in,
                              void* d_out, int out_size) {
    const float* x    = (const float*)d_in[0];
    const float* diag = (const float*)d_in[1];
    const float* wl   = (const float*)d_in[2];
    const float* wrt  = (const float*)d_in[3];
    const float* br   = (const float*)d_in[4];
    const float* bias = (const float*)d_in[5];
    float* out = (float*)d_out;

    prep<<<3088, 256>>>(wl, wrt, diag, br, bias);
    k1_lowrank<<<1024, 256>>>(x);
    k1b_reduce<<<2048, 256>>>();
    k2_output<<<dim3(64, 64), 256>>>(x, out);
}

// round 12
// speedup vs baseline: 1.5991x; 1.5991x over previous
#include <cuda_runtime.h>
#include <cuda_bf16.h>
#include <cstdint>

// ==========================================================================
// LORI_FC: out = x @ blockdiag(D) + (x @ Wl^T) @ Wr^T + (b_right + bias)
//   x [8192,4096] f32. Split-bf16 hi/lo (3 passes), HMMA m16n8k16, f32 accum.
// Coalesced LDG -> swizzled STS -> ldmatrix.x4 -> MMA.  No fragment LDGs.
//   prep: split Wl/Wr/D^T -> bf16 hi/lo, bsum = br + bias
//   k1:   t_part[s] = x[:, ks:ks+1024] @ Wl^T slice   (256 CTAs)
//   k1b:  t = sum partials -> bf16 hi/lo
//   k2:   out[128,64j] = xb_j @ D_j + t @ Wr_j^T + bsum  (4096 CTAs)
// ==========================================================================

#define M_ROWS 8192
#define IN_F   4096
#define OUT_F  4096
#define KSPLIT 4

__device__ __align__(16) float g_tpart[KSPLIT][M_ROWS * 64];       // 8 MB
__device__ __align__(16) __nv_bfloat16 g_thi[M_ROWS * 64];
__device__ __align__(16) __nv_bfloat16 g_tlo[M_ROWS * 64];
__device__ __align__(16) __nv_bfloat16 g_wlh[64 * IN_F];
__device__ __align__(16) __nv_bfloat16 g_wll[64 * IN_F];
__device__ __align__(16) __nv_bfloat16 g_wrh[OUT_F * 64];
__device__ __align__(16) __nv_bfloat16 g_wrl[OUT_F * 64];
__device__ __align__(16) __nv_bfloat16 g_dth[64 * 64 * 64];        // [j][n][k]
__device__ __align__(16) __nv_bfloat16 g_dtl[64 * 64 * 64];
__device__ __align__(16) float g_bsum[OUT_F];

// smem layout (dynamic, 48 KB): Ah 16K | Al 16K | Bh 8K | Bl 8K
#define SM_AH 0
#define SM_AL 16384
#define SM_BH 32768
#define SM_BL 40960
#define SMEM_BYTES 49152

#define MMA_BF16(C, A, B0, B1)                                                \
    asm volatile(                                                             \
        "mma.sync.aligned.m16n8k16.row.col.f32.bf16.bf16.f32 "                \
        "{%0,%1,%2,%3}, {%4,%5,%6,%7}, {%8,%9}, {%0,%1,%2,%3};"               \
        : "+f"((C)[0]), "+f"((C)[1]), "+f"((C)[2]), "+f"((C)[3])              \
        : "r"((A)[0]), "r"((A)[1]), "r"((A)[2]), "r"((A)[3]), "r"(B0), "r"(B1))

#define LDSM4(R, A)                                                           \
    asm volatile("ldmatrix.sync.aligned.m8n8.x4.shared.b16 {%0,%1,%2,%3}, [%4];" \
        : "=r"((R)[0]), "=r"((R)[1]), "=r"((R)[2]), "=r"((R)[3]) : "r"(A))

__device__ __forceinline__ uint32_t smem_u32(const void* p) {
    uint32_t a;
    asm("{ .reg .u64 t; cvta.to.shared.u64 t, %1; cvt.u32.u64 %0, t; }"
        : "=r"(a) : "l"(p));
    return a;
}

// split float2 -> packed bf16x2 hi + lo (lo = bf16 of residual)
__device__ __forceinline__ void split2pack(float f0, float f1,
                                           uint32_t& hi, uint32_t& lo) {
    uint32_t h;
    asm("cvt.rn.bf16x2.f32 %0, %1, %2;" : "=r"(h) : "f"(f1), "f"(f0));
    float h0 = __uint_as_float(h << 16);
    float h1 = __uint_as_float(h & 0xffff0000u);
    float r0 = f0 - h0, r1 = f1 - h1;
    asm("cvt.rn.bf16x2.f32 %0, %1, %2;" : "=r"(lo) : "f"(r1), "f"(r0));
    hi = h;
}

// ---------------- staging helpers (coalesced LDG -> swizzled STS) ---------
// A tile hi/lo: 128 rows x 64 cols bf16, 128B rows, XOR-swizzled by (row&7)<<4.
// B tile hi/lo:  64 rows x 64 cols bf16.

// x block 128x64 f32 -> split -> A tiles
__device__ __forceinline__ void stage_x(uint32_t sb, const float* xp, int tid) {
    const int r = tid >> 1, h = tid & 1;
    const float* p = xp + (size_t)r * IN_F + h * 32;
    const uint32_t dbase = sb + SM_AH + (uint32_t)r * 128 + (uint32_t)h * 64;
    const uint32_t xv = (uint32_t)(r & 7) << 4;
#pragma unroll
    for (int i = 0; i < 8; i++) {
        float4 v = ((const float4*)p)[i];
        uint32_t h0, l0, h1, l1;
        split2pack(v.x, v.y, h0, l0);
        split2pack(v.z, v.w, h1, l1);
        uint32_t d = (dbase + i * 8) ^ xv;
        asm volatile("st.shared.v2.b32 [%0], {%1,%2};" :: "r"(d), "r"(h0), "r"(h1));
        asm volatile("st.shared.v2.b32 [%0], {%1,%2};" :: "r"(d + 16384), "r"(l0), "r"(l1));
    }
}

// pre-split bf16 [64][64] contiguous -> B tiles
__device__ __forceinline__ void stage_B64(uint32_t sb, const __nv_bfloat16* hi,
                                          const __nv_bfloat16* lo, int tid) {
#pragma unroll
    for (int c = tid; c < 512; c += 256) {
        uint4 v = ((const uint4*)hi)[c];
        uint4 w = ((const uint4*)lo)[c];
        uint32_t d = (sb + SM_BH + (uint32_t)c * 16) ^ ((((uint32_t)c >> 3) & 7) << 4);
        asm volatile("st.shared.v4.b32 [%0], {%1,%2,%3,%4};"
                     :: "r"(d), "r"(v.x), "r"(v.y), "r"(v.z), "r"(v.w));
        asm volatile("st.shared.v4.b32 [%0], {%1,%2,%3,%4};"
                     :: "r"(d + 8192), "r"(w.x), "r"(w.y), "r"(w.z), "r"(w.w));
    }
}

// Wl chunk: 64 rows, row stride IN_F, cols [kbase, kbase+64) -> B tiles
__device__ __forceinline__ void stage_Bwl(uint32_t sb, int kbase, int tid) {
#pragma unroll
    for (int c = tid; c < 512; c += 256) {
        int n = c >> 3, kp = c & 7;
        uint4 v = *(const uint4*)(g_wlh + (size_t)n * IN_F + kbase + kp * 8);
        uint4 w = *(const uint4*)(g_wll + (size_t)n * IN_F + kbase + kp * 8);
        uint32_t d = (sb + SM_BH + (uint32_t)c * 16) ^ (((uint32_t)n & 7) << 4);
        asm volatile("st.shared.v4.b32 [%0], {%1,%2,%3,%4};"
                     :: "r"(d), "r"(v.x), "r"(v.y), "r"(v.z), "r"(v.w));
        asm volatile("st.shared.v4.b32 [%0], {%1,%2,%3,%4};"
                     :: "r"(d + 8192), "r"(w.x), "r"(w.y), "r"(w.z), "r"(w.w));
    }
}

// pre-split t hi/lo 128x64 contiguous -> A tiles
__device__ __forceinline__ void stage_At(uint32_t sb, const __nv_bfloat16* hi,
                                         const __nv_bfloat16* lo, int tid) {
#pragma unroll
    for (int c = tid; c < 1024; c += 256) {
        uint4 v = ((const uint4*)hi)[c];
        uint4 w = ((const uint4*)lo)[c];
        uint32_t d = (sb + SM_AH + (uint32_t)c * 16) ^ ((((uint32_t)c >> 3) & 7) << 4);
        asm volatile("st.shared.v4.b32 [%0], {%1,%2,%3,%4};"
                     :: "r"(d), "r"(v.x), "r"(v.y), "r"(v.z), "r"(v.w));
        asm volatile("st.shared.v4.b32 [%0], {%1,%2,%3,%4};"
                     :: "r"(d + 16384), "r"(w.x), "r"(w.y), "r"(w.z), "r"(w.w));
    }
}

// ---------------- core: one K=64 GEMM (128x64 tile), 3-pass split ---------
__device__ __forceinline__ void gemm64(uint32_t sb, int mrow, int ncol, int lane,
                                       float (&acc)[2][4][4]) {
    const uint32_t xv = (uint32_t)(lane & 7) << 4;
    const uint32_t abase = sb + SM_AH + ((uint32_t)mrow + (uint32_t)(lane & 15)) * 128
                         + (uint32_t)(lane >> 4) * 16;
    const uint32_t bbase = sb + SM_BH
                         + ((uint32_t)ncol + (uint32_t)((lane & 7) + ((lane >> 4) << 3))) * 128
                         + (uint32_t)((lane & 8) << 1);
#pragma unroll
    for (int kk = 0; kk < 4; kk++) {
        const uint32_t k2b = kk * 32;
        uint32_t ah[2][4], al[2][4], bh[2][4], bl[2][4];
#pragma unroll
        for (int mf = 0; mf < 2; mf++) {
            uint32_t a = (abase + mf * 2048 + k2b) ^ xv;
            LDSM4(ah[mf], a);
            LDSM4(al[mf], a + 16384);
        }
#pragma unroll
        for (int nb = 0; nb < 2; nb++) {
            uint32_t a = (bbase + nb * 2048 + k2b) ^ xv;
            LDSM4(bh[nb], a);
            LDSM4(bl[nb], a + 8192);
        }
#pragma unroll
        for (int mf = 0; mf < 2; mf++)
#pragma unroll
            for (int nf = 0; nf < 4; nf++) {
                uint32_t B0 = bh[nf >> 1][(nf & 1) * 2], B1 = bh[nf >> 1][(nf & 1) * 2 + 1];
                uint32_t L0 = bl[nf >> 1][(nf & 1) * 2], L1 = bl[nf >> 1][(nf & 1) * 2 + 1];
                MMA_BF16(acc[mf][nf], ah[mf], B0, B1);
                MMA_BF16(acc[mf][nf], ah[mf], L0, L1);
                MMA_BF16(acc[mf][nf], al[mf], B0, B1);
            }
    }
}

// --------------------------------------------------------------------------
// prep: weight splits + bsum
// --------------------------------------------------------------------------
__global__ void prep(const float* __restrict__ wl, const float* __restrict__ wr,
                     const float* __restrict__ diag, const float* __restrict__ br,
                     const float* __restrict__ bias) {
    int i = blockIdx.x * 256 + threadIdx.x;
    if (i < 262144) {
        float v = wl[i];
        __nv_bfloat16 h = __float2bfloat16(v);
        g_wlh[i] = h;
        g_wll[i] = __float2bfloat16(v - __bfloat162float(h));
    } else if (i < 524288) {
        int k = i - 262144;
        float v = wr[k];
        __nv_bfloat16 h = __float2bfloat16(v);
        g_wrh[k] = h;
        g_wrl[k] = __float2bfloat16(v - __bfloat162float(h));
    } else if (i < 786432) {
        int k = i - 524288;             // dt layout [j][n][kk]
        int j = k >> 12, r = k & 4095, n = r >> 6, kk = r & 63;
        float v = diag[(size_t)j * 4096 + (size_t)kk * 64 + n];
        __nv_bfloat16 h = __float2bfloat16(v);
        g_dth[k] = h;
        g_dtl[k] = __float2bfloat16(v - __bfloat162float(h));
    } else if (i < 786432 + 4096) {
        int k = i - 786432;
        g_bsum[k] = br[k] + bias[k];
    }
}

// --------------------------------------------------------------------------
// k1: t_part[s] = x[:, s*1024:(s+1)*1024] @ Wl^T slice.
// grid 256 (= 64 m-tiles x 4 k-splits), 256 threads.
// --------------------------------------------------------------------------
__global__ void __launch_bounds__(256, 2)
k1_lowrank(const float* __restrict__ x) {
    extern __shared__ __align__(16) char smc[];
    const uint32_t sb = smem_u32(smc);
    const int tid = threadIdx.x, w = tid >> 5, lane = tid & 31;
    const int g = lane >> 2, q = lane & 3;
    const int m0 = (blockIdx.x >> 2) * 128;
    const int ks = (blockIdx.x & 3) * 1024;
    const int mrow = (w & 3) * 32, ncol = (w >> 2) * 32;

    float acc[2][4][4];
#pragma unroll
    for (int mf = 0; mf < 2; mf++)
#pragma unroll
        for (int nf = 0; nf < 4; nf++)
#pragma unroll
            for (int c = 0; c < 4; c++) acc[mf][nf][c] = 0.0f;

    for (int c = 0; c < 16; c++) {
        stage_x(sb, x + (size_t)m0 * IN_F + ks + c * 64, tid);
        stage_Bwl(sb, ks + c * 64, tid);
        __syncthreads();
        gemm64(sb, mrow, ncol, lane, acc);
        __syncthreads();
    }

    float* tp = g_tpart[blockIdx.x & 3];
#pragma unroll
    for (int mf = 0; mf < 2; mf++)
#pragma unroll
        for (int nf = 0; nf < 4; nf++) {
            int row = m0 + mrow + mf * 16 + g;
            int col = ncol + nf * 8 + q * 2;
            *(float2*)&tp[(size_t)row * 64 + col] =
                make_float2(acc[mf][nf][0], acc[mf][nf][1]);
            *(float2*)&tp[(size_t)(row + 8) * 64 + col] =
                make_float2(acc[mf][nf][2], acc[mf][nf][3]);
        }
}

// --------------------------------------------------------------------------
// k1b: t = sum of partials -> bf16 hi/lo
// --------------------------------------------------------------------------
__global__ void k1b_reduce() {
    int i = blockIdx.x * 256 + threadIdx.x;
    float s = 0.0f;
#pragma unroll
    for (int p = 0; p < KSPLIT; p++) s += g_tpart[p][i];
    __nv_bfloat16 h = __float2bfloat16(s);
    g_thi[i] = h;
    g_tlo[i] = __float2bfloat16(s - __bfloat162float(h));
}

// --------------------------------------------------------------------------
// k2: out[m0:m0+128, 64j:64j+64] = xb_j @ D_j + t @ Wr_j^T + bsum
// grid (64 m, 64 j), 256 threads, 2 CTAs/SM.
// --------------------------------------------------------------------------
__global__ void __launch_bounds__(256, 2)
k2_output(const float* __restrict__ x, float* __restrict__ out) {
    extern __shared__ __align__(16) char smc[];
    const uint32_t sb = smem_u32(smc);
    const int tid = threadIdx.x, w = tid >> 5, lane = tid & 31;
    const int g = lane >> 2, q = lane & 3;
    const int m0 = blockIdx.x * 128;
    const int j  = blockIdx.y;
    const int mrow = (w & 3) * 32, ncol = (w >> 2) * 32;

    float acc[2][4][4];
#pragma unroll
    for (int mf = 0; mf < 2; mf++)
#pragma unroll
        for (int nf = 0; nf < 4; nf++)
#pragma unroll
            for (int c = 0; c < 4; c++) acc[mf][nf][c] = 0.0f;

    // GEMM 1: A = x[:, 64j:64j+64], B = D_j^T
    stage_x(sb, x + (size_t)m0 * IN_F + j * 64, tid);
    stage_B64(sb, g_dth + (size_t)j * 4096, g_dtl + (size_t)j * 4096, tid);
    __syncthreads();
    gemm64(sb, mrow, ncol, lane, acc);
    __syncthreads();

    // GEMM 2: A = t (pre-split), B = Wr_j
    stage_At(sb, g_thi + (size_t)m0 * 64, g_tlo + (size_t)m0 * 64, tid);
    stage_B64(sb, g_wrh + (size_t)j * 4096, g_wrl + (size_t)j * 4096, tid);
    __syncthreads();
    gemm64(sb, mrow, ncol, lane, acc);

    // epilogue: + bsum
    const float* bs = g_bsum + j * 64;
#pragma unroll
    for (int mf = 0; mf < 2; mf++)
#pragma unroll
        for (int nf = 0; nf < 4; nf++) {
            int col = ncol + nf * 8 + q * 2;
            int row = m0 + mrow + mf * 16 + g;
            float2 b = *(const float2*)(bs + col);
            *(float2*)&out[(size_t)row * OUT_F + j * 64 + col] =
                make_float2(acc[mf][nf][0] + b.x, acc[mf][nf][1] + b.y);
            *(float2*)&out[(size_t)(row + 8) * OUT_F + j * 64 + col] =
                make_float2(acc[mf][nf][2] + b.x, acc[mf][nf][3] + b.y);
        }
}

// --------------------------------------------------------------------------
extern "C" void kernel_launch(void* const* d_in, const int* in_sizes, int n_in,
                              void* d_out, int out_size) {
    const float* x    = (const float*)d_in[0];
    const float* diag = (const float*)d_in[1];
    const float* wl   = (const float*)d_in[2];
    const float* wrt  = (const float*)d_in[3];
    const float* br   = (const float*)d_in[4];
    const float* bias = (const float*)d_in[5];
    float* out = (float*)d_out;

    cudaFuncSetAttribute(k1_lowrank, cudaFuncAttributeMaxDynamicSharedMemorySize, SMEM_BYTES);
    cudaFuncSetAttribute(k2_output,  cudaFuncAttributeMaxDynamicSharedMemorySize, SMEM_BYTES);

    prep<<<3088, 256>>>(wl, wrt, diag, br, bias);
    k1_lowrank<<<256, 256, SMEM_BYTES>>>(x);
    k1b_reduce<<<2048, 256>>>();
    k2_output<<<dim3(64, 64), 256, SMEM_BYTES>>>(x, out);
}